// round 13
// baseline (speedup 1.0000x reference)
#include <cuda_runtime.h>
#include <cuda_bf16.h>
#include <cstdint>

#define NN 50000
#define NE 800000
#define CC 128
#define NL 4
#define BN_EPS 1e-5f
#define NC4 (NN * (CC / 4))

// ---------------- scratch (static device globals; no allocation) ----------------
__device__ int   g_is64;
__device__ __align__(16) int   g_ideg[NN];
__device__ __align__(16) float g_dinv[NN];
__device__ __align__(16) int   g_colptr[NN + 1];
__device__ __align__(16) int   g_cursor[NN];
__device__ __align__(16) int   g_src[NE];
__device__ __align__(16) float g_w[NE];
__device__ __align__(16) float g_h[NN * CC];
__device__ __align__(16) float g_agg[NN * CC];
__device__ __align__(16) float g_sum[CC];
__device__ __align__(16) float g_sq[CC];
__device__ __align__(16) float g_scale[CC];
__device__ __align__(16) float g_shift[CC];
// W transposed + bf16 hi/lo split: Wt[l][n][k] (n = out channel, k contiguous)
__device__ __align__(16) __nv_bfloat16 g_wt_hi[NL * CC * CC];
__device__ __align__(16) __nv_bfloat16 g_wt_lo[NL * CC * CC];

// ---------------- helpers ----------------
__device__ __forceinline__ uint32_t bf2pack(float a, float b) {
    __nv_bfloat162 t = __floats2bfloat162_rn(a, b);   // x=a (low), y=b (high)
    return *(uint32_t*)&t;
}
// mma.sync m16n8k16 row.col bf16 -> fp32 accumulate (baseline PTX, sm_80+)
__device__ __forceinline__ void mma16816(float* d, const uint32_t* a, uint32_t b0, uint32_t b1) {
    asm volatile(
        "mma.sync.aligned.m16n8k16.row.col.f32.bf16.bf16.f32 "
        "{%0,%1,%2,%3}, {%4,%5,%6,%7}, {%8,%9}, {%0,%1,%2,%3};"
        : "+f"(d[0]), "+f"(d[1]), "+f"(d[2]), "+f"(d[3])
        : "r"(a[0]), "r"(a[1]), "r"(a[2]), "r"(a[3]), "r"(b0), "r"(b1));
}

// ---------------- dtype detection ----------------
__global__ void k_detect(const int* __restrict__ ei32) {
    int ornz = 0;
    #pragma unroll 8
    for (int j = 0; j < 256; j++) ornz |= ei32[2 * j + 1];
    g_is64 = (ornz == 0) ? 1 : 0;
}
__device__ __forceinline__ int edge_at(const int* ei32, int is64, long long idx) {
    return is64 ? ei32[2 * idx] : ei32[idx];
}

// ---------------- prolog ----------------
__global__ void k_deg_init() {
    int i = blockIdx.x * blockDim.x + threadIdx.x;
    if (i < NN) g_ideg[i] = 0;
    if (i < CC) { g_sum[i] = 0.f; g_sq[i] = 0.f; }
}
__global__ void k_deg(const int* __restrict__ ei32) {
    int e = blockIdx.x * blockDim.x + threadIdx.x;
    if (e < NE) {
        int c = edge_at(ei32, g_is64, (long long)NE + e);
        if ((unsigned)c < NN) atomicAdd(&g_ideg[c], 1);
    }
}
__global__ void k_dinv() {
    int i = blockIdx.x * blockDim.x + threadIdx.x;
    if (i < NN) g_dinv[i] = rsqrtf((float)(g_ideg[i] + 1));
}
__global__ void k_scan() {
    __shared__ int sh[1024];
    const int tid = threadIdx.x;
    const int per = 49;
    const int base = tid * per;
    int s = 0;
    for (int j = 0; j < per; j++) { int idx = base + j; if (idx < NN) s += g_ideg[idx]; }
    sh[tid] = s;
    __syncthreads();
    for (int d = 1; d < 1024; d <<= 1) {
        int v = (tid >= d) ? sh[tid - d] : 0;
        __syncthreads();
        sh[tid] += v;
        __syncthreads();
    }
    int run = (tid > 0) ? sh[tid - 1] : 0;
    for (int j = 0; j < per; j++) {
        int idx = base + j;
        if (idx < NN) { g_colptr[idx] = run; g_cursor[idx] = run; run += g_ideg[idx]; }
    }
    if (tid == 1023) g_colptr[NN] = sh[1023];
}
__global__ void k_fill(const int* __restrict__ ei32) {
    int e = blockIdx.x * blockDim.x + threadIdx.x;
    if (e < NE) {
        int is64 = g_is64;
        int r = edge_at(ei32, is64, e);
        int c = edge_at(ei32, is64, (long long)NE + e);
        if ((unsigned)r < NN && (unsigned)c < NN) {
            int pos = atomicAdd(&g_cursor[c], 1);
            g_src[pos] = r;
            g_w[pos] = g_dinv[r] * g_dinv[c];
        }
    }
}
// transpose + bf16 hi/lo split of all layer weights: Wt[l][n][k] = W[l][k][n]
__global__ void k_wprep(const float* __restrict__ W) {
    int idx = blockIdx.x * blockDim.x + threadIdx.x;
    if (idx < NL * CC * CC) {
        int l = idx / (CC * CC);
        int rem = idx - l * CC * CC;
        int n = rem / CC;
        int k = rem - n * CC;
        float v = W[(size_t)(l * CC + k) * CC + n];
        __nv_bfloat16 hi = __float2bfloat16_rn(v);
        float lo = v - __bfloat162float(hi);
        g_wt_hi[idx] = hi;
        g_wt_lo[idx] = __float2bfloat16_rn(lo);
    }
}

// ---------------- GEMM: H = X @ W via mma.sync bf16 hi/lo split ----------------
// Block = 128 threads (4 warps), 64-row M-tile. X tile converted to bf16 hi/lo in
// SMEM (fused BN+ReLU for layers>0). Each warp: 16 rows x 128 cols output.
// D = Xhi*Whi + Xhi*Wlo + Xlo*Whi (fp32 accum) -> fp32-class accuracy.
// B fragments loaded straight from g_wt_hi/lo (L1/L2-hot, shared by all blocks).
__global__ void __launch_bounds__(128) k_gemm(const float* __restrict__ Xext,
                                              int layer, int fused)
{
    __shared__ __align__(16) uint32_t s_hi[64 * CC / 2];   // 64 rows x 64 bf16x2 = 16KB
    __shared__ __align__(16) uint32_t s_lo[64 * CC / 2];   // 16KB
    __shared__ float s_scale[CC], s_shift[CC];

    const int tid = threadIdx.x;
    const int row0 = blockIdx.x * 64;

    if (fused && tid < CC) { s_scale[tid] = g_scale[tid]; s_shift[tid] = g_shift[tid]; }
    __syncthreads();

    {   // convert X tile -> hi/lo bf16 (zero-pad tail rows)
        const float4* src = fused ? ((const float4*)g_agg + (size_t)row0 * 32)
                                  : ((const float4*)(Xext + (size_t)row0 * CC));
        int rows = NN - row0; if (rows > 64) rows = 64;
        int n4 = rows * 32;
        #pragma unroll
        for (int i = 0; i < 16; i++) {
            int idx = tid + 128 * i;               // float4 index within tile
            float4 v = make_float4(0.f, 0.f, 0.f, 0.f);
            if (idx < n4) v = src[idx];
            if (fused) {
                int ch = idx & 31;
                float4 sc = ((const float4*)s_scale)[ch];
                float4 sh = ((const float4*)s_shift)[ch];
                v.x = fmaxf(fmaf(v.x, sc.x, sh.x), 0.f);
                v.y = fmaxf(fmaf(v.y, sc.y, sh.y), 0.f);
                v.z = fmaxf(fmaf(v.z, sc.z, sh.z), 0.f);
                v.w = fmaxf(fmaf(v.w, sc.w, sh.w), 0.f);
            }
            __nv_bfloat162 h0 = __floats2bfloat162_rn(v.x, v.y);
            __nv_bfloat162 h1 = __floats2bfloat162_rn(v.z, v.w);
            s_hi[idx * 2 + 0] = *(uint32_t*)&h0;
            s_hi[idx * 2 + 1] = *(uint32_t*)&h1;
            float rx = v.x - __low2float(h0),  ry = v.y - __high2float(h0);
            float rz = v.z - __low2float(h1),  rw = v.w - __high2float(h1);
            s_lo[idx * 2 + 0] = bf2pack(rx, ry);
            s_lo[idx * 2 + 1] = bf2pack(rz, rw);
        }
    }
    __syncthreads();

    const int wid = tid >> 5;
    const int lane = tid & 31;
    const int g = lane >> 2;        // group id (0..7)
    const int tg = lane & 3;        // thread-in-group (0..3)
    const int mrow = wid * 16;      // warp's row base within tile

    float acc[16][4];
    #pragma unroll
    for (int nt = 0; nt < 16; nt++)
        acc[nt][0] = acc[nt][1] = acc[nt][2] = acc[nt][3] = 0.f;

    const uint32_t* whi = (const uint32_t*)(g_wt_hi + (size_t)layer * CC * CC);
    const uint32_t* wlo = (const uint32_t*)(g_wt_lo + (size_t)layer * CC * CC);
    // Wt row n: 64 bf16x2 words; word (n, kp) = k elements {2kp, 2kp+1}

    const int ro = (mrow + g) * 64;        // bf16x2 row offsets in SMEM
    const int r8 = (mrow + g + 8) * 64;

    #pragma unroll
    for (int ks = 0; ks < 8; ks++) {       // k block = 16, kp base = ks*8
        int kp = ks * 8 + tg;
        uint32_t ahi[4], alo[4];
        ahi[0] = s_hi[ro + kp];     ahi[1] = s_hi[r8 + kp];
        ahi[2] = s_hi[ro + kp + 4]; ahi[3] = s_hi[r8 + kp + 4];
        alo[0] = s_lo[ro + kp];     alo[1] = s_lo[r8 + kp];
        alo[2] = s_lo[ro + kp + 4]; alo[3] = s_lo[r8 + kp + 4];

        #pragma unroll
        for (int nt = 0; nt < 16; nt++) {
            int n = nt * 8 + g;
            uint32_t bh0 = __ldg(&whi[n * 64 + kp]);
            uint32_t bh1 = __ldg(&whi[n * 64 + kp + 4]);
            uint32_t bl0 = __ldg(&wlo[n * 64 + kp]);
            uint32_t bl1 = __ldg(&wlo[n * 64 + kp + 4]);
            mma16816(acc[nt], ahi, bh0, bh1);
            mma16816(acc[nt], ahi, bl0, bl1);
            mma16816(acc[nt], alo, bh0, bh1);
        }
    }

    // epilogue: c0/c1 -> (row g, col tg*2+{0,1}); c2/c3 -> row g+8
    int r1 = row0 + mrow + g;
    int r2 = r1 + 8;
    #pragma unroll
    for (int nt = 0; nt < 16; nt++) {
        int col = nt * 8 + tg * 2;
        if (r1 < NN) *(float2*)&g_h[(size_t)r1 * CC + col] = make_float2(acc[nt][0], acc[nt][1]);
        if (r2 < NN) *(float2*)&g_h[(size_t)r2 * CC + col] = make_float2(acc[nt][2], acc[nt][3]);
    }
}

// ---------------- aggregation + fused BN stats (round-9 proven) ----------------
__global__ void __launch_bounds__(256) k_aggregate()
{
    __shared__ float ssum[CC], ssq[CC];
    const int tid = threadIdx.x;
    if (tid < CC) { ssum[tid] = 0.f; ssq[tid] = 0.f; }
    __syncthreads();

    const int gw = (blockIdx.x * 256 + tid) >> 5;
    const int lane = tid & 31;
    const int nw = (gridDim.x * 256) >> 5;

    float s0 = 0, s1 = 0, s2 = 0, s3 = 0;
    float q0 = 0, q1 = 0, q2 = 0, q3 = 0;

    for (int i = gw; i < NN; i += nw) {
        float di = __ldg(&g_dinv[i]);
        float s2i = di * di;
        float4 v = __ldg((const float4*)(g_h + (size_t)i * CC) + lane);
        float4 acc = make_float4(v.x * s2i, v.y * s2i, v.z * s2i, v.w * s2i);

        int e0 = __ldg(&g_colptr[i]);
        int e1 = __ldg(&g_colptr[i + 1]);

        int e = e0;
        for (; e + 3 < e1; e += 4) {
            int   sA = __ldg(&g_src[e]);
            int   sB = __ldg(&g_src[e + 1]);
            int   sC = __ldg(&g_src[e + 2]);
            int   sD = __ldg(&g_src[e + 3]);
            float wA = __ldg(&g_w[e]);
            float wB = __ldg(&g_w[e + 1]);
            float wC = __ldg(&g_w[e + 2]);
            float wD = __ldg(&g_w[e + 3]);
            float4 uA = __ldg((const float4*)(g_h + (size_t)sA * CC) + lane);
            float4 uB = __ldg((const float4*)(g_h + (size_t)sB * CC) + lane);
            float4 uC = __ldg((const float4*)(g_h + (size_t)sC * CC) + lane);
            float4 uD = __ldg((const float4*)(g_h + (size_t)sD * CC) + lane);
            acc.x = fmaf(uA.x, wA, acc.x); acc.y = fmaf(uA.y, wA, acc.y);
            acc.z = fmaf(uA.z, wA, acc.z); acc.w = fmaf(uA.w, wA, acc.w);
            acc.x = fmaf(uB.x, wB, acc.x); acc.y = fmaf(uB.y, wB, acc.y);
            acc.z = fmaf(uB.z, wB, acc.z); acc.w = fmaf(uB.w, wB, acc.w);
            acc.x = fmaf(uC.x, wC, acc.x); acc.y = fmaf(uC.y, wC, acc.y);
            acc.z = fmaf(uC.z, wC, acc.z); acc.w = fmaf(uC.w, wC, acc.w);
            acc.x = fmaf(uD.x, wD, acc.x); acc.y = fmaf(uD.y, wD, acc.y);
            acc.z = fmaf(uD.z, wD, acc.z); acc.w = fmaf(uD.w, wD, acc.w);
        }
        for (; e < e1; e++) {
            int   s = __ldg(&g_src[e]);
            float wgt = __ldg(&g_w[e]);
            float4 u = __ldg((const float4*)(g_h + (size_t)s * CC) + lane);
            acc.x = fmaf(u.x, wgt, acc.x); acc.y = fmaf(u.y, wgt, acc.y);
            acc.z = fmaf(u.z, wgt, acc.z); acc.w = fmaf(u.w, wgt, acc.w);
        }

        *((float4*)(g_agg + (size_t)i * CC) + lane) = acc;

        s0 += acc.x; s1 += acc.y; s2 += acc.z; s3 += acc.w;
        q0 += acc.x * acc.x; q1 += acc.y * acc.y;
        q2 += acc.z * acc.z; q3 += acc.w * acc.w;
    }

    int ch = lane * 4;
    atomicAdd(&ssum[ch + 0], s0); atomicAdd(&ssum[ch + 1], s1);
    atomicAdd(&ssum[ch + 2], s2); atomicAdd(&ssum[ch + 3], s3);
    atomicAdd(&ssq[ch + 0], q0);  atomicAdd(&ssq[ch + 1], q1);
    atomicAdd(&ssq[ch + 2], q2);  atomicAdd(&ssq[ch + 3], q3);
    __syncthreads();
    if (tid < CC) {
        atomicAdd(&g_sum[tid], ssum[tid]);
        atomicAdd(&g_sq[tid], ssq[tid]);
    }
}

// ---------------- finalize BN params ----------------
__global__ void k_finalize(const float* __restrict__ gamma, const float* __restrict__ beta)
{
    int c = threadIdx.x;
    float mu = g_sum[c] * (1.0f / NN);
    float var = g_sq[c] * (1.0f / NN) - mu * mu;
    float rstd = rsqrtf(var + BN_EPS);
    float sc = rstd * gamma[c];
    g_scale[c] = sc;
    g_shift[c] = beta[c] - mu * sc;
    g_sum[c] = 0.f; g_sq[c] = 0.f;
}

// ---------------- final normalize + relu -> out ----------------
__global__ void __launch_bounds__(256) k_norm_relu(float* __restrict__ OUT)
{
    __shared__ float4 ssc[32], ssh[32];
    const int tid = threadIdx.x;
    if (tid < 32) {
        ssc[tid] = ((const float4*)g_scale)[tid];
        ssh[tid] = ((const float4*)g_shift)[tid];
    }
    __syncthreads();
    const int stride = gridDim.x * 256;
    const float4* A = (const float4*)g_agg;
    float4* O = (float4*)OUT;
    for (int f = blockIdx.x * 256 + tid; f < NC4; f += stride) {
        int ch = f & 31;
        float4 v = A[f];
        float4 sc = ssc[ch];
        float4 sh = ssh[ch];
        float4 o;
        o.x = fmaxf(fmaf(v.x, sc.x, sh.x), 0.f);
        o.y = fmaxf(fmaf(v.y, sc.y, sh.y), 0.f);
        o.z = fmaxf(fmaf(v.z, sc.z, sh.z), 0.f);
        o.w = fmaxf(fmaf(v.w, sc.w, sh.w), 0.f);
        O[f] = o;
    }
}

// ---------------- launch ----------------
extern "C" void kernel_launch(void* const* d_in, const int* in_sizes, int n_in,
                              void* d_out, int out_size)
{
    const float* x     = (const float*)d_in[0];
    const int*   ei32  = (const int*)d_in[1];
    const float* W     = (const float*)d_in[2];
    const float* gamma = (const float*)d_in[4];
    const float* beta  = (const float*)d_in[5];
    float*       out   = (float*)d_out;

    k_detect<<<1, 1>>>(ei32);
    k_deg_init<<<(NN + 255) / 256, 256>>>();
    k_deg<<<(NE + 255) / 256, 256>>>(ei32);
    k_dinv<<<(NN + 255) / 256, 256>>>();
    k_scan<<<1, 1024>>>();
    k_fill<<<(NE + 255) / 256, 256>>>(ei32);
    k_wprep<<<(NL * CC * CC + 255) / 256, 256>>>(W);

    const int GEMM_BLOCKS = (NN + 63) / 64;   // 782
    const int AGG_BLOCKS  = 1184;
    const int EW_BLOCKS   = 1184;

    for (int l = 0; l < NL; l++) {
        k_gemm<<<GEMM_BLOCKS, 128>>>(x, l, (l != 0));
        k_aggregate<<<AGG_BLOCKS, 256>>>();
        k_finalize<<<1, CC>>>(gamma + l * CC, beta + l * CC);
    }
    k_norm_relu<<<EW_BLOCKS, 256>>>(out);
    (void)in_sizes; (void)n_in; (void)out_size;
}

// round 14
// speedup vs baseline: 1.3319x; 1.3319x over previous
#include <cuda_runtime.h>
#include <cuda_bf16.h>
#include <cstdint>

#define NN 50000
#define NE 800000
#define CC 128
#define NL 4
#define BN_EPS 1e-5f
#define NC4 (NN * (CC / 4))
#define SW 68   // padded row stride in 32-bit words: bank = (4*row + kp) % 32 -> conflict-free

// ---------------- scratch (static device globals; no allocation) ----------------
__device__ int   g_is64;
__device__ __align__(16) int   g_ideg[NN];
__device__ __align__(16) float g_dinv[NN];
__device__ __align__(16) int   g_colptr[NN + 1];
__device__ __align__(16) int   g_cursor[NN];
__device__ __align__(16) int   g_src[NE];
__device__ __align__(16) float g_w[NE];
__device__ __align__(16) float g_h[NN * CC];
__device__ __align__(16) float g_agg[NN * CC];
__device__ __align__(16) float g_sum[CC];
__device__ __align__(16) float g_sq[CC];
__device__ __align__(16) float g_scale[CC];
__device__ __align__(16) float g_shift[CC];
// W transposed + bf16 hi/lo split: Wt[l][n][k] (n = out channel, k contiguous)
__device__ __align__(16) __nv_bfloat16 g_wt_hi[NL * CC * CC];
__device__ __align__(16) __nv_bfloat16 g_wt_lo[NL * CC * CC];

// ---------------- helpers ----------------
__device__ __forceinline__ uint32_t bf2pack(float a, float b) {
    __nv_bfloat162 t = __floats2bfloat162_rn(a, b);
    return *(uint32_t*)&t;
}
// mma.sync m16n8k16 row.col bf16 -> fp32 accumulate (baseline PTX, sm_80+)
__device__ __forceinline__ void mma16816(float* d, const uint32_t* a, uint32_t b0, uint32_t b1) {
    asm volatile(
        "mma.sync.aligned.m16n8k16.row.col.f32.bf16.bf16.f32 "
        "{%0,%1,%2,%3}, {%4,%5,%6,%7}, {%8,%9}, {%0,%1,%2,%3};"
        : "+f"(d[0]), "+f"(d[1]), "+f"(d[2]), "+f"(d[3])
        : "r"(a[0]), "r"(a[1]), "r"(a[2]), "r"(a[3]), "r"(b0), "r"(b1));
}

// ---------------- dtype detection ----------------
__global__ void k_detect(const int* __restrict__ ei32) {
    int ornz = 0;
    #pragma unroll 8
    for (int j = 0; j < 256; j++) ornz |= ei32[2 * j + 1];
    g_is64 = (ornz == 0) ? 1 : 0;
}
__device__ __forceinline__ int edge_at(const int* ei32, int is64, long long idx) {
    return is64 ? ei32[2 * idx] : ei32[idx];
}

// ---------------- prolog ----------------
__global__ void k_deg_init() {
    int i = blockIdx.x * blockDim.x + threadIdx.x;
    if (i < NN) g_ideg[i] = 0;
    if (i < CC) { g_sum[i] = 0.f; g_sq[i] = 0.f; }
}
__global__ void k_deg(const int* __restrict__ ei32) {
    int e = blockIdx.x * blockDim.x + threadIdx.x;
    if (e < NE) {
        int c = edge_at(ei32, g_is64, (long long)NE + e);
        if ((unsigned)c < NN) atomicAdd(&g_ideg[c], 1);
    }
}
__global__ void k_dinv() {
    int i = blockIdx.x * blockDim.x + threadIdx.x;
    if (i < NN) g_dinv[i] = rsqrtf((float)(g_ideg[i] + 1));
}
__global__ void k_scan() {
    __shared__ int sh[1024];
    const int tid = threadIdx.x;
    const int per = 49;
    const int base = tid * per;
    int s = 0;
    for (int j = 0; j < per; j++) { int idx = base + j; if (idx < NN) s += g_ideg[idx]; }
    sh[tid] = s;
    __syncthreads();
    for (int d = 1; d < 1024; d <<= 1) {
        int v = (tid >= d) ? sh[tid - d] : 0;
        __syncthreads();
        sh[tid] += v;
        __syncthreads();
    }
    int run = (tid > 0) ? sh[tid - 1] : 0;
    for (int j = 0; j < per; j++) {
        int idx = base + j;
        if (idx < NN) { g_colptr[idx] = run; g_cursor[idx] = run; run += g_ideg[idx]; }
    }
    if (tid == 1023) g_colptr[NN] = sh[1023];
}
__global__ void k_fill(const int* __restrict__ ei32) {
    int e = blockIdx.x * blockDim.x + threadIdx.x;
    if (e < NE) {
        int is64 = g_is64;
        int r = edge_at(ei32, is64, e);
        int c = edge_at(ei32, is64, (long long)NE + e);
        if ((unsigned)r < NN && (unsigned)c < NN) {
            int pos = atomicAdd(&g_cursor[c], 1);
            g_src[pos] = r;
            g_w[pos] = g_dinv[r] * g_dinv[c];
        }
    }
}
// transpose + bf16 hi/lo split of all layer weights: Wt[l][n][k] = W[l][k][n]
__global__ void k_wprep(const float* __restrict__ W) {
    int idx = blockIdx.x * blockDim.x + threadIdx.x;
    if (idx < NL * CC * CC) {
        int l = idx / (CC * CC);
        int rem = idx - l * CC * CC;
        int n = rem / CC;
        int k = rem - n * CC;
        float v = W[(size_t)(l * CC + k) * CC + n];
        __nv_bfloat16 hi = __float2bfloat16_rn(v);
        float lo = v - __bfloat162float(hi);
        g_wt_hi[idx] = hi;
        g_wt_lo[idx] = __float2bfloat16_rn(lo);
    }
}

// ---------------- GEMM: H = X @ W via mma.sync bf16 hi/lo split ----------------
// Round-13 fragment logic (VALIDATED, rel_err 1.5e-5) with fixed data movement:
//   - A fragments hoisted to registers (loaded once from padded, conflict-free SMEM)
//   - W staged per 16-column chunk in padded SMEM; B fragment reads are
//     conflict-free LDS instead of 512 scalar LDGs per thread.
__global__ void __launch_bounds__(128) k_gemm(const float* __restrict__ Xext,
                                              int layer, int fused)
{
    __shared__ __align__(16) uint32_t s_hi[64 * SW];    // 17408 B
    __shared__ __align__(16) uint32_t s_lo[64 * SW];    // 17408 B
    __shared__ __align__(16) uint32_t s_whi[16 * SW];   // 4352 B (W chunk hi)
    __shared__ __align__(16) uint32_t s_wlo[16 * SW];   // 4352 B (W chunk lo)
    __shared__ float s_scale[CC], s_shift[CC];

    const int tid = threadIdx.x;
    const int row0 = blockIdx.x * 64;

    if (fused && tid < CC) { s_scale[tid] = g_scale[tid]; s_shift[tid] = g_shift[tid]; }
    __syncthreads();

    {   // convert X tile -> hi/lo bf16 into padded SMEM (zero-pad tail rows)
        const float4* src = fused ? ((const float4*)g_agg + (size_t)row0 * 32)
                                  : ((const float4*)(Xext + (size_t)row0 * CC));
        int rows = NN - row0; if (rows > 64) rows = 64;
        int n4 = rows * 32;
        #pragma unroll
        for (int i = 0; i < 16; i++) {
            int idx = tid + 128 * i;               // float4 index: row=idx>>5, c4=idx&31
            float4 v = make_float4(0.f, 0.f, 0.f, 0.f);
            if (idx < n4) v = src[idx];
            if (fused) {
                int ch = idx & 31;
                float4 sc = ((const float4*)s_scale)[ch];
                float4 sh = ((const float4*)s_shift)[ch];
                v.x = fmaxf(fmaf(v.x, sc.x, sh.x), 0.f);
                v.y = fmaxf(fmaf(v.y, sc.y, sh.y), 0.f);
                v.z = fmaxf(fmaf(v.z, sc.z, sh.z), 0.f);
                v.w = fmaxf(fmaf(v.w, sc.w, sh.w), 0.f);
            }
            int row = idx >> 5, c4 = idx & 31;
            int w0 = row * SW + c4 * 2;
            __nv_bfloat162 h0 = __floats2bfloat162_rn(v.x, v.y);
            __nv_bfloat162 h1 = __floats2bfloat162_rn(v.z, v.w);
            s_hi[w0 + 0] = *(uint32_t*)&h0;
            s_hi[w0 + 1] = *(uint32_t*)&h1;
            float rx = v.x - __low2float(h0),  ry = v.y - __high2float(h0);
            float rz = v.z - __low2float(h1),  rw = v.w - __high2float(h1);
            s_lo[w0 + 0] = bf2pack(rx, ry);
            s_lo[w0 + 1] = bf2pack(rz, rw);
        }
    }
    __syncthreads();

    const int wid = tid >> 5;
    const int lane = tid & 31;
    const int g = lane >> 2;        // 0..7
    const int tg = lane & 3;        // 0..3
    const int mrow = wid * 16;

    // hoist all A fragments (8 k-steps) into registers
    uint32_t ahi[8][4], alo[8][4];
    {
        const int ro = (mrow + g) * SW;
        const int r8 = (mrow + g + 8) * SW;
        #pragma unroll
        for (int ks = 0; ks < 8; ks++) {
            int kp = ks * 8 + tg;
            ahi[ks][0] = s_hi[ro + kp];     ahi[ks][1] = s_hi[r8 + kp];
            ahi[ks][2] = s_hi[ro + kp + 4]; ahi[ks][3] = s_hi[r8 + kp + 4];
            alo[ks][0] = s_lo[ro + kp];     alo[ks][1] = s_lo[r8 + kp];
            alo[ks][2] = s_lo[ro + kp + 4]; alo[ks][3] = s_lo[r8 + kp + 4];
        }
    }

    float acc[16][4];
    #pragma unroll
    for (int nt = 0; nt < 16; nt++)
        acc[nt][0] = acc[nt][1] = acc[nt][2] = acc[nt][3] = 0.f;

    const uint4* whi = (const uint4*)(g_wt_hi + (size_t)layer * CC * CC);
    const uint4* wlo = (const uint4*)(g_wt_lo + (size_t)layer * CC * CC);
    // global Wt row n = 64 words = 16 uint4

    for (int c = 0; c < 8; c++) {          // 8 chunks of 16 output columns
        __syncthreads();
        {   // stage W chunk rows [16c, 16c+16) into padded SMEM
            int nl = tid >> 3;             // 0..15
            int seg = tid & 7;             // 0..7  (8 words = 2 uint4 per thread)
            int gsrc = (16 * c + nl) * 16 + seg * 2;   // uint4 index
            uint4 a = __ldg(&whi[gsrc]);
            uint4 b = __ldg(&whi[gsrc + 1]);
            uint4 e = __ldg(&wlo[gsrc]);
            uint4 f = __ldg(&wlo[gsrc + 1]);
            int dst = nl * SW + seg * 8;
            *(uint4*)&s_whi[dst] = a;
            *(uint4*)&s_whi[dst + 4] = b;
            *(uint4*)&s_wlo[dst] = e;
            *(uint4*)&s_wlo[dst + 4] = f;
        }
        __syncthreads();

        #pragma unroll
        for (int ks = 0; ks < 8; ks++) {
            int kp = ks * 8 + tg;
            #pragma unroll
            for (int ntl = 0; ntl < 2; ntl++) {
                int nloc = ntl * 8 + g;
                uint32_t bh0 = s_whi[nloc * SW + kp];
                uint32_t bh1 = s_whi[nloc * SW + kp + 4];
                uint32_t bl0 = s_wlo[nloc * SW + kp];
                uint32_t bl1 = s_wlo[nloc * SW + kp + 4];
                float* a = acc[c * 2 + ntl];
                mma16816(a, ahi[ks], bh0, bh1);
                mma16816(a, ahi[ks], bl0, bl1);
                mma16816(a, alo[ks], bh0, bh1);
            }
        }
    }

    // epilogue: c0/c1 -> (row g, col tg*2+{0,1}); c2/c3 -> row g+8
    int r1 = row0 + mrow + g;
    int r2 = r1 + 8;
    #pragma unroll
    for (int nt = 0; nt < 16; nt++) {
        int col = nt * 8 + tg * 2;
        if (r1 < NN) *(float2*)&g_h[(size_t)r1 * CC + col] = make_float2(acc[nt][0], acc[nt][1]);
        if (r2 < NN) *(float2*)&g_h[(size_t)r2 * CC + col] = make_float2(acc[nt][2], acc[nt][3]);
    }
}

// ---------------- aggregation + fused BN stats (round-9 proven) ----------------
__global__ void __launch_bounds__(256) k_aggregate()
{
    __shared__ float ssum[CC], ssq[CC];
    const int tid = threadIdx.x;
    if (tid < CC) { ssum[tid] = 0.f; ssq[tid] = 0.f; }
    __syncthreads();

    const int gw = (blockIdx.x * 256 + tid) >> 5;
    const int lane = tid & 31;
    const int nw = (gridDim.x * 256) >> 5;

    float s0 = 0, s1 = 0, s2 = 0, s3 = 0;
    float q0 = 0, q1 = 0, q2 = 0, q3 = 0;

    for (int i = gw; i < NN; i += nw) {
        float di = __ldg(&g_dinv[i]);
        float s2i = di * di;
        float4 v = __ldg((const float4*)(g_h + (size_t)i * CC) + lane);
        float4 acc = make_float4(v.x * s2i, v.y * s2i, v.z * s2i, v.w * s2i);

        int e0 = __ldg(&g_colptr[i]);
        int e1 = __ldg(&g_colptr[i + 1]);

        int e = e0;
        for (; e + 3 < e1; e += 4) {
            int   sA = __ldg(&g_src[e]);
            int   sB = __ldg(&g_src[e + 1]);
            int   sC = __ldg(&g_src[e + 2]);
            int   sD = __ldg(&g_src[e + 3]);
            float wA = __ldg(&g_w[e]);
            float wB = __ldg(&g_w[e + 1]);
            float wC = __ldg(&g_w[e + 2]);
            float wD = __ldg(&g_w[e + 3]);
            float4 uA = __ldg((const float4*)(g_h + (size_t)sA * CC) + lane);
            float4 uB = __ldg((const float4*)(g_h + (size_t)sB * CC) + lane);
            float4 uC = __ldg((const float4*)(g_h + (size_t)sC * CC) + lane);
            float4 uD = __ldg((const float4*)(g_h + (size_t)sD * CC) + lane);
            acc.x = fmaf(uA.x, wA, acc.x); acc.y = fmaf(uA.y, wA, acc.y);
            acc.z = fmaf(uA.z, wA, acc.z); acc.w = fmaf(uA.w, wA, acc.w);
            acc.x = fmaf(uB.x, wB, acc.x); acc.y = fmaf(uB.y, wB, acc.y);
            acc.z = fmaf(uB.z, wB, acc.z); acc.w = fmaf(uB.w, wB, acc.w);
            acc.x = fmaf(uC.x, wC, acc.x); acc.y = fmaf(uC.y, wC, acc.y);
            acc.z = fmaf(uC.z, wC, acc.z); acc.w = fmaf(uC.w, wC, acc.w);
            acc.x = fmaf(uD.x, wD, acc.x); acc.y = fmaf(uD.y, wD, acc.y);
            acc.z = fmaf(uD.z, wD, acc.z); acc.w = fmaf(uD.w, wD, acc.w);
        }
        for (; e < e1; e++) {
            int   s = __ldg(&g_src[e]);
            float wgt = __ldg(&g_w[e]);
            float4 u = __ldg((const float4*)(g_h + (size_t)s * CC) + lane);
            acc.x = fmaf(u.x, wgt, acc.x); acc.y = fmaf(u.y, wgt, acc.y);
            acc.z = fmaf(u.z, wgt, acc.z); acc.w = fmaf(u.w, wgt, acc.w);
        }

        *((float4*)(g_agg + (size_t)i * CC) + lane) = acc;

        s0 += acc.x; s1 += acc.y; s2 += acc.z; s3 += acc.w;
        q0 += acc.x * acc.x; q1 += acc.y * acc.y;
        q2 += acc.z * acc.z; q3 += acc.w * acc.w;
    }

    int ch = lane * 4;
    atomicAdd(&ssum[ch + 0], s0); atomicAdd(&ssum[ch + 1], s1);
    atomicAdd(&ssum[ch + 2], s2); atomicAdd(&ssum[ch + 3], s3);
    atomicAdd(&ssq[ch + 0], q0);  atomicAdd(&ssq[ch + 1], q1);
    atomicAdd(&ssq[ch + 2], q2);  atomicAdd(&ssq[ch + 3], q3);
    __syncthreads();
    if (tid < CC) {
        atomicAdd(&g_sum[tid], ssum[tid]);
        atomicAdd(&g_sq[tid], ssq[tid]);
    }
}

// ---------------- finalize BN params ----------------
__global__ void k_finalize(const float* __restrict__ gamma, const float* __restrict__ beta)
{
    int c = threadIdx.x;
    float mu = g_sum[c] * (1.0f / NN);
    float var = g_sq[c] * (1.0f / NN) - mu * mu;
    float rstd = rsqrtf(var + BN_EPS);
    float sc = rstd * gamma[c];
    g_scale[c] = sc;
    g_shift[c] = beta[c] - mu * sc;
    g_sum[c] = 0.f; g_sq[c] = 0.f;
}

// ---------------- final normalize + relu -> out ----------------
__global__ void __launch_bounds__(256) k_norm_relu(float* __restrict__ OUT)
{
    __shared__ float4 ssc[32], ssh[32];
    const int tid = threadIdx.x;
    if (tid < 32) {
        ssc[tid] = ((const float4*)g_scale)[tid];
        ssh[tid] = ((const float4*)g_shift)[tid];
    }
    __syncthreads();
    const int stride = gridDim.x * 256;
    const float4* A = (const float4*)g_agg;
    float4* O = (float4*)OUT;
    for (int f = blockIdx.x * 256 + tid; f < NC4; f += stride) {
        int ch = f & 31;
        float4 v = A[f];
        float4 sc = ssc[ch];
        float4 sh = ssh[ch];
        float4 o;
        o.x = fmaxf(fmaf(v.x, sc.x, sh.x), 0.f);
        o.y = fmaxf(fmaf(v.y, sc.y, sh.y), 0.f);
        o.z = fmaxf(fmaf(v.z, sc.z, sh.z), 0.f);
        o.w = fmaxf(fmaf(v.w, sc.w, sh.w), 0.f);
        O[f] = o;
    }
}

// ---------------- launch ----------------
extern "C" void kernel_launch(void* const* d_in, const int* in_sizes, int n_in,
                              void* d_out, int out_size)
{
    const float* x     = (const float*)d_in[0];
    const int*   ei32  = (const int*)d_in[1];
    const float* W     = (const float*)d_in[2];
    const float* gamma = (const float*)d_in[4];
    const float* beta  = (const float*)d_in[5];
    float*       out   = (float*)d_out;

    k_detect<<<1, 1>>>(ei32);
    k_deg_init<<<(NN + 255) / 256, 256>>>();
    k_deg<<<(NE + 255) / 256, 256>>>(ei32);
    k_dinv<<<(NN + 255) / 256, 256>>>();
    k_scan<<<1, 1024>>>();
    k_fill<<<(NE + 255) / 256, 256>>>(ei32);
    k_wprep<<<(NL * CC * CC + 255) / 256, 256>>>(W);

    const int GEMM_BLOCKS = (NN + 63) / 64;   // 782
    const int AGG_BLOCKS  = 1184;
    const int EW_BLOCKS   = 1184;

    for (int l = 0; l < NL; l++) {
        k_gemm<<<GEMM_BLOCKS, 128>>>(x, l, (l != 0));
        k_aggregate<<<AGG_BLOCKS, 256>>>();
        k_finalize<<<1, CC>>>(gamma + l * CC, beta + l * CC);
    }
    k_norm_relu<<<EW_BLOCKS, 256>>>(out);
    (void)in_sizes; (void)n_in; (void)out_size;
}

// round 15
// speedup vs baseline: 1.4655x; 1.1003x over previous
#include <cuda_runtime.h>
#include <cuda_bf16.h>
#include <cstdint>

#define NN 50000
#define NE 800000
#define CC 128
#define NL 4
#define BN_EPS 1e-5f
#define NC4 (NN * (CC / 4))
#define SW 68   // padded row stride in 32-bit words: bank = (4*row + kp) % 32 -> conflict-free

// ---------------- scratch (static device globals; no allocation) ----------------
__device__ int   g_is64;
__device__ __align__(16) int   g_ideg[NN];
__device__ __align__(16) float g_dinv[NN];
__device__ __align__(16) int   g_colptr[NN + 1];
__device__ __align__(16) int   g_cursor[NN];
__device__ __align__(16) int   g_src[NE];
__device__ __align__(16) float g_w[NE];
__device__ __align__(16) float g_h[NN * CC];
__device__ __align__(16) float g_agg[NN * CC];
__device__ __align__(16) float g_sum[CC];
__device__ __align__(16) float g_sq[CC];
__device__ __align__(16) float g_scale[CC];
__device__ __align__(16) float g_shift[CC];
// W transposed + bf16 hi/lo split: Wt[l][n][k] (n = out channel, k contiguous)
__device__ __align__(16) __nv_bfloat16 g_wt_hi[NL * CC * CC];
__device__ __align__(16) __nv_bfloat16 g_wt_lo[NL * CC * CC];

// ---------------- helpers ----------------
__device__ __forceinline__ uint32_t bf2pack(float a, float b) {
    __nv_bfloat162 t = __floats2bfloat162_rn(a, b);
    return *(uint32_t*)&t;
}
// mma.sync m16n8k16 row.col bf16 -> fp32 accumulate (baseline PTX, sm_80+)
__device__ __forceinline__ void mma16816(float* d, const uint32_t* a, uint32_t b0, uint32_t b1) {
    asm volatile(
        "mma.sync.aligned.m16n8k16.row.col.f32.bf16.bf16.f32 "
        "{%0,%1,%2,%3}, {%4,%5,%6,%7}, {%8,%9}, {%0,%1,%2,%3};"
        : "+f"(d[0]), "+f"(d[1]), "+f"(d[2]), "+f"(d[3])
        : "r"(a[0]), "r"(a[1]), "r"(a[2]), "r"(a[3]), "r"(b0), "r"(b1));
}

// ---------------- dtype detection ----------------
__global__ void k_detect(const int* __restrict__ ei32) {
    int ornz = 0;
    #pragma unroll 8
    for (int j = 0; j < 256; j++) ornz |= ei32[2 * j + 1];
    g_is64 = (ornz == 0) ? 1 : 0;
}
__device__ __forceinline__ int edge_at(const int* ei32, int is64, long long idx) {
    return is64 ? ei32[2 * idx] : ei32[idx];
}

// ---------------- prolog ----------------
__global__ void k_deg_init() {
    int i = blockIdx.x * blockDim.x + threadIdx.x;
    if (i < NN) g_ideg[i] = 0;
    if (i < CC) { g_sum[i] = 0.f; g_sq[i] = 0.f; }
}
__global__ void k_deg(const int* __restrict__ ei32) {
    int e = blockIdx.x * blockDim.x + threadIdx.x;
    if (e < NE) {
        int c = edge_at(ei32, g_is64, (long long)NE + e);
        if ((unsigned)c < NN) atomicAdd(&g_ideg[c], 1);
    }
}
__global__ void k_dinv() {
    int i = blockIdx.x * blockDim.x + threadIdx.x;
    if (i < NN) g_dinv[i] = rsqrtf((float)(g_ideg[i] + 1));
}
__global__ void k_scan() {
    __shared__ int sh[1024];
    const int tid = threadIdx.x;
    const int per = 49;
    const int base = tid * per;
    int s = 0;
    for (int j = 0; j < per; j++) { int idx = base + j; if (idx < NN) s += g_ideg[idx]; }
    sh[tid] = s;
    __syncthreads();
    for (int d = 1; d < 1024; d <<= 1) {
        int v = (tid >= d) ? sh[tid - d] : 0;
        __syncthreads();
        sh[tid] += v;
        __syncthreads();
    }
    int run = (tid > 0) ? sh[tid - 1] : 0;
    for (int j = 0; j < per; j++) {
        int idx = base + j;
        if (idx < NN) { g_colptr[idx] = run; g_cursor[idx] = run; run += g_ideg[idx]; }
    }
    if (tid == 1023) g_colptr[NN] = sh[1023];
}
__global__ void k_fill(const int* __restrict__ ei32) {
    int e = blockIdx.x * blockDim.x + threadIdx.x;
    if (e < NE) {
        int is64 = g_is64;
        int r = edge_at(ei32, is64, e);
        int c = edge_at(ei32, is64, (long long)NE + e);
        if ((unsigned)r < NN && (unsigned)c < NN) {
            int pos = atomicAdd(&g_cursor[c], 1);
            g_src[pos] = r;
            g_w[pos] = g_dinv[r] * g_dinv[c];
        }
    }
}
// transpose + bf16 hi/lo split of all layer weights: Wt[l][n][k] = W[l][k][n]
__global__ void k_wprep(const float* __restrict__ W) {
    int idx = blockIdx.x * blockDim.x + threadIdx.x;
    if (idx < NL * CC * CC) {
        int l = idx / (CC * CC);
        int rem = idx - l * CC * CC;
        int n = rem / CC;
        int k = rem - n * CC;
        float v = W[(size_t)(l * CC + k) * CC + n];
        __nv_bfloat16 hi = __float2bfloat16_rn(v);
        float lo = v - __bfloat162float(hi);
        g_wt_hi[idx] = hi;
        g_wt_lo[idx] = __float2bfloat16_rn(lo);
    }
}

// ---------------- GEMM: H = X @ W via mma.sync bf16 hi/lo split ----------------
// Round-14 validated layout + per-chunk accumulator writeback: acc shrinks from
// 64 persistent regs to 8, __launch_bounds__(128,4) -> 4 blocks/SM (16 warps),
// doubling occupancy on the tensor pipe.
__global__ void __launch_bounds__(128, 4) k_gemm(const float* __restrict__ Xext,
                                                 int layer, int fused)
{
    __shared__ __align__(16) uint32_t s_hi[64 * SW];    // 17408 B
    __shared__ __align__(16) uint32_t s_lo[64 * SW];    // 17408 B
    __shared__ __align__(16) uint32_t s_whi[16 * SW];   // 4352 B (W chunk hi)
    __shared__ __align__(16) uint32_t s_wlo[16 * SW];   // 4352 B (W chunk lo)
    __shared__ float s_scale[CC], s_shift[CC];

    const int tid = threadIdx.x;
    const int row0 = blockIdx.x * 64;

    if (fused && tid < CC) { s_scale[tid] = g_scale[tid]; s_shift[tid] = g_shift[tid]; }
    __syncthreads();

    {   // convert X tile -> hi/lo bf16 into padded SMEM (zero-pad tail rows)
        const float4* src = fused ? ((const float4*)g_agg + (size_t)row0 * 32)
                                  : ((const float4*)(Xext + (size_t)row0 * CC));
        int rows = NN - row0; if (rows > 64) rows = 64;
        int n4 = rows * 32;
        #pragma unroll
        for (int i = 0; i < 16; i++) {
            int idx = tid + 128 * i;               // float4 index: row=idx>>5, c4=idx&31
            float4 v = make_float4(0.f, 0.f, 0.f, 0.f);
            if (idx < n4) v = src[idx];
            if (fused) {
                int ch = idx & 31;
                float4 sc = ((const float4*)s_scale)[ch];
                float4 sh = ((const float4*)s_shift)[ch];
                v.x = fmaxf(fmaf(v.x, sc.x, sh.x), 0.f);
                v.y = fmaxf(fmaf(v.y, sc.y, sh.y), 0.f);
                v.z = fmaxf(fmaf(v.z, sc.z, sh.z), 0.f);
                v.w = fmaxf(fmaf(v.w, sc.w, sh.w), 0.f);
            }
            int row = idx >> 5, c4 = idx & 31;
            int w0 = row * SW + c4 * 2;
            __nv_bfloat162 h0 = __floats2bfloat162_rn(v.x, v.y);
            __nv_bfloat162 h1 = __floats2bfloat162_rn(v.z, v.w);
            s_hi[w0 + 0] = *(uint32_t*)&h0;
            s_hi[w0 + 1] = *(uint32_t*)&h1;
            float rx = v.x - __low2float(h0),  ry = v.y - __high2float(h0);
            float rz = v.z - __low2float(h1),  rw = v.w - __high2float(h1);
            s_lo[w0 + 0] = bf2pack(rx, ry);
            s_lo[w0 + 1] = bf2pack(rz, rw);
        }
    }
    __syncthreads();

    const int wid = tid >> 5;
    const int lane = tid & 31;
    const int g = lane >> 2;        // 0..7
    const int tg = lane & 3;        // 0..3
    const int mrow = wid * 16;

    // hoist all A fragments (8 k-steps) into registers
    uint32_t ahi[8][4], alo[8][4];
    {
        const int ro = (mrow + g) * SW;
        const int r8 = (mrow + g + 8) * SW;
        #pragma unroll
        for (int ks = 0; ks < 8; ks++) {
            int kp = ks * 8 + tg;
            ahi[ks][0] = s_hi[ro + kp];     ahi[ks][1] = s_hi[r8 + kp];
            ahi[ks][2] = s_hi[ro + kp + 4]; ahi[ks][3] = s_hi[r8 + kp + 4];
            alo[ks][0] = s_lo[ro + kp];     alo[ks][1] = s_lo[r8 + kp];
            alo[ks][2] = s_lo[ro + kp + 4]; alo[ks][3] = s_lo[r8 + kp + 4];
        }
    }

    const uint4* whi = (const uint4*)(g_wt_hi + (size_t)layer * CC * CC);
    const uint4* wlo = (const uint4*)(g_wt_lo + (size_t)layer * CC * CC);
    const int r1 = row0 + mrow + g;
    const int r2 = r1 + 8;

    for (int c = 0; c < 8; c++) {          // 8 chunks of 16 output columns
        __syncthreads();
        {   // stage W chunk rows [16c, 16c+16) into padded SMEM
            int nl = tid >> 3;             // 0..15
            int seg = tid & 7;             // 0..7  (8 words = 2 uint4 per thread)
            int gsrc = (16 * c + nl) * 16 + seg * 2;   // uint4 index
            uint4 a = __ldg(&whi[gsrc]);
            uint4 b = __ldg(&whi[gsrc + 1]);
            uint4 e = __ldg(&wlo[gsrc]);
            uint4 f = __ldg(&wlo[gsrc + 1]);
            int dst = nl * SW + seg * 8;
            *(uint4*)&s_whi[dst] = a;
            *(uint4*)&s_whi[dst + 4] = b;
            *(uint4*)&s_wlo[dst] = e;
            *(uint4*)&s_wlo[dst + 4] = f;
        }
        __syncthreads();

        float acc[2][4];
        acc[0][0] = acc[0][1] = acc[0][2] = acc[0][3] = 0.f;
        acc[1][0] = acc[1][1] = acc[1][2] = acc[1][3] = 0.f;

        #pragma unroll
        for (int ks = 0; ks < 8; ks++) {
            int kp = ks * 8 + tg;
            #pragma unroll
            for (int ntl = 0; ntl < 2; ntl++) {
                int nloc = ntl * 8 + g;
                uint32_t bh0 = s_whi[nloc * SW + kp];
                uint32_t bh1 = s_whi[nloc * SW + kp + 4];
                uint32_t bl0 = s_wlo[nloc * SW + kp];
                uint32_t bl1 = s_wlo[nloc * SW + kp + 4];
                mma16816(acc[ntl], ahi[ks], bh0, bh1);
                mma16816(acc[ntl], ahi[ks], bl0, bl1);
                mma16816(acc[ntl], alo[ks], bh0, bh1);
            }
        }

        // per-chunk epilogue: c0/c1 -> (row g, col tg*2); c2/c3 -> row g+8
        #pragma unroll
        for (int ntl = 0; ntl < 2; ntl++) {
            int col = c * 16 + ntl * 8 + tg * 2;
            if (r1 < NN) *(float2*)&g_h[(size_t)r1 * CC + col] = make_float2(acc[ntl][0], acc[ntl][1]);
            if (r2 < NN) *(float2*)&g_h[(size_t)r2 * CC + col] = make_float2(acc[ntl][2], acc[ntl][3]);
        }
    }
}

// ---------------- aggregation + fused BN stats (round-9 proven) ----------------
__global__ void __launch_bounds__(256) k_aggregate()
{
    __shared__ float ssum[CC], ssq[CC];
    const int tid = threadIdx.x;
    if (tid < CC) { ssum[tid] = 0.f; ssq[tid] = 0.f; }
    __syncthreads();

    const int gw = (blockIdx.x * 256 + tid) >> 5;
    const int lane = tid & 31;
    const int nw = (gridDim.x * 256) >> 5;

    float s0 = 0, s1 = 0, s2 = 0, s3 = 0;
    float q0 = 0, q1 = 0, q2 = 0, q3 = 0;

    for (int i = gw; i < NN; i += nw) {
        float di = __ldg(&g_dinv[i]);
        float s2i = di * di;
        float4 v = __ldg((const float4*)(g_h + (size_t)i * CC) + lane);
        float4 acc = make_float4(v.x * s2i, v.y * s2i, v.z * s2i, v.w * s2i);

        int e0 = __ldg(&g_colptr[i]);
        int e1 = __ldg(&g_colptr[i + 1]);

        int e = e0;
        for (; e + 3 < e1; e += 4) {
            int   sA = __ldg(&g_src[e]);
            int   sB = __ldg(&g_src[e + 1]);
            int   sC = __ldg(&g_src[e + 2]);
            int   sD = __ldg(&g_src[e + 3]);
            float wA = __ldg(&g_w[e]);
            float wB = __ldg(&g_w[e + 1]);
            float wC = __ldg(&g_w[e + 2]);
            float wD = __ldg(&g_w[e + 3]);
            float4 uA = __ldg((const float4*)(g_h + (size_t)sA * CC) + lane);
            float4 uB = __ldg((const float4*)(g_h + (size_t)sB * CC) + lane);
            float4 uC = __ldg((const float4*)(g_h + (size_t)sC * CC) + lane);
            float4 uD = __ldg((const float4*)(g_h + (size_t)sD * CC) + lane);
            acc.x = fmaf(uA.x, wA, acc.x); acc.y = fmaf(uA.y, wA, acc.y);
            acc.z = fmaf(uA.z, wA, acc.z); acc.w = fmaf(uA.w, wA, acc.w);
            acc.x = fmaf(uB.x, wB, acc.x); acc.y = fmaf(uB.y, wB, acc.y);
            acc.z = fmaf(uB.z, wB, acc.z); acc.w = fmaf(uB.w, wB, acc.w);
            acc.x = fmaf(uC.x, wC, acc.x); acc.y = fmaf(uC.y, wC, acc.y);
            acc.z = fmaf(uC.z, wC, acc.z); acc.w = fmaf(uC.w, wC, acc.w);
            acc.x = fmaf(uD.x, wD, acc.x); acc.y = fmaf(uD.y, wD, acc.y);
            acc.z = fmaf(uD.z, wD, acc.z); acc.w = fmaf(uD.w, wD, acc.w);
        }
        for (; e < e1; e++) {
            int   s = __ldg(&g_src[e]);
            float wgt = __ldg(&g_w[e]);
            float4 u = __ldg((const float4*)(g_h + (size_t)s * CC) + lane);
            acc.x = fmaf(u.x, wgt, acc.x); acc.y = fmaf(u.y, wgt, acc.y);
            acc.z = fmaf(u.z, wgt, acc.z); acc.w = fmaf(u.w, wgt, acc.w);
        }

        *((float4*)(g_agg + (size_t)i * CC) + lane) = acc;

        s0 += acc.x; s1 += acc.y; s2 += acc.z; s3 += acc.w;
        q0 += acc.x * acc.x; q1 += acc.y * acc.y;
        q2 += acc.z * acc.z; q3 += acc.w * acc.w;
    }

    int ch = lane * 4;
    atomicAdd(&ssum[ch + 0], s0); atomicAdd(&ssum[ch + 1], s1);
    atomicAdd(&ssum[ch + 2], s2); atomicAdd(&ssum[ch + 3], s3);
    atomicAdd(&ssq[ch + 0], q0);  atomicAdd(&ssq[ch + 1], q1);
    atomicAdd(&ssq[ch + 2], q2);  atomicAdd(&ssq[ch + 3], q3);
    __syncthreads();
    if (tid < CC) {
        atomicAdd(&g_sum[tid], ssum[tid]);
        atomicAdd(&g_sq[tid], ssq[tid]);
    }
}

// ---------------- finalize BN params ----------------
__global__ void k_finalize(const float* __restrict__ gamma, const float* __restrict__ beta)
{
    int c = threadIdx.x;
    float mu = g_sum[c] * (1.0f / NN);
    float var = g_sq[c] * (1.0f / NN) - mu * mu;
    float rstd = rsqrtf(var + BN_EPS);
    float sc = rstd * gamma[c];
    g_scale[c] = sc;
    g_shift[c] = beta[c] - mu * sc;
    g_sum[c] = 0.f; g_sq[c] = 0.f;
}

// ---------------- final normalize + relu -> out ----------------
__global__ void __launch_bounds__(256) k_norm_relu(float* __restrict__ OUT)
{
    __shared__ float4 ssc[32], ssh[32];
    const int tid = threadIdx.x;
    if (tid < 32) {
        ssc[tid] = ((const float4*)g_scale)[tid];
        ssh[tid] = ((const float4*)g_shift)[tid];
    }
    __syncthreads();
    const int stride = gridDim.x * 256;
    const float4* A = (const float4*)g_agg;
    float4* O = (float4*)OUT;
    for (int f = blockIdx.x * 256 + tid; f < NC4; f += stride) {
        int ch = f & 31;
        float4 v = A[f];
        float4 sc = ssc[ch];
        float4 sh = ssh[ch];
        float4 o;
        o.x = fmaxf(fmaf(v.x, sc.x, sh.x), 0.f);
        o.y = fmaxf(fmaf(v.y, sc.y, sh.y), 0.f);
        o.z = fmaxf(fmaf(v.z, sc.z, sh.z), 0.f);
        o.w = fmaxf(fmaf(v.w, sc.w, sh.w), 0.f);
        O[f] = o;
    }
}

// ---------------- launch ----------------
extern "C" void kernel_launch(void* const* d_in, const int* in_sizes, int n_in,
                              void* d_out, int out_size)
{
    const float* x     = (const float*)d_in[0];
    const int*   ei32  = (const int*)d_in[1];
    const float* W     = (const float*)d_in[2];
    const float* gamma = (const float*)d_in[4];
    const float* beta  = (const float*)d_in[5];
    float*       out   = (float*)d_out;

    k_detect<<<1, 1>>>(ei32);
    k_deg_init<<<(NN + 255) / 256, 256>>>();
    k_deg<<<(NE + 255) / 256, 256>>>(ei32);
    k_dinv<<<(NN + 255) / 256, 256>>>();
    k_scan<<<1, 1024>>>();
    k_fill<<<(NE + 255) / 256, 256>>>(ei32);
    k_wprep<<<(NL * CC * CC + 255) / 256, 256>>>(W);

    const int GEMM_BLOCKS = (NN + 63) / 64;   // 782
    const int AGG_BLOCKS  = 1184;
    const int EW_BLOCKS   = 1184;

    for (int l = 0; l < NL; l++) {
        k_gemm<<<GEMM_BLOCKS, 128>>>(x, l, (l != 0));
        k_aggregate<<<AGG_BLOCKS, 256>>>();
        k_finalize<<<1, CC>>>(gamma + l * CC, beta + l * CC);
    }
    k_norm_relu<<<EW_BLOCKS, 256>>>(out);
    (void)in_sizes; (void)n_in; (void)out_size;
}

// round 16
// speedup vs baseline: 1.5961x; 1.0891x over previous
#include <cuda_runtime.h>
#include <cuda_bf16.h>
#include <cuda_fp16.h>
#include <cstdint>

#define NN 50000
#define NE 800000
#define CC 128
#define NL 4
#define BN_EPS 1e-5f
#define NC4 (NN * (CC / 4))
#define SW 68   // padded row stride in 32-bit words: bank = (4*row + kp) % 32 -> conflict-free

// ---------------- scratch (static device globals; no allocation) ----------------
__device__ int   g_is64;
__device__ __align__(16) int   g_ideg[NN];
__device__ __align__(16) float g_dinv[NN];
__device__ __align__(16) int   g_colptr[NN + 1];
__device__ __align__(16) int   g_cursor[NN];
__device__ __align__(16) int   g_src[NE];
__device__ __align__(16) float g_w[NE];
__device__ __align__(16) __half g_h[NN * CC];    // messages in fp16 (halves gather traffic)
__device__ __align__(16) float g_agg[NN * CC];
__device__ __align__(16) float g_sum[CC];
__device__ __align__(16) float g_sq[CC];
__device__ __align__(16) float g_scale[CC];
__device__ __align__(16) float g_shift[CC];
// W transposed + bf16 hi/lo split: Wt[l][n][k] (n = out channel, k contiguous)
__device__ __align__(16) __nv_bfloat16 g_wt_hi[NL * CC * CC];
__device__ __align__(16) __nv_bfloat16 g_wt_lo[NL * CC * CC];

// ---------------- helpers ----------------
__device__ __forceinline__ uint32_t bf2pack(float a, float b) {
    __nv_bfloat162 t = __floats2bfloat162_rn(a, b);
    return *(uint32_t*)&t;
}
// mma.sync m16n8k16 row.col bf16 -> fp32 accumulate (baseline PTX, sm_80+)
__device__ __forceinline__ void mma16816(float* d, const uint32_t* a, uint32_t b0, uint32_t b1) {
    asm volatile(
        "mma.sync.aligned.m16n8k16.row.col.f32.bf16.bf16.f32 "
        "{%0,%1,%2,%3}, {%4,%5,%6,%7}, {%8,%9}, {%0,%1,%2,%3};"
        : "+f"(d[0]), "+f"(d[1]), "+f"(d[2]), "+f"(d[3])
        : "r"(a[0]), "r"(a[1]), "r"(a[2]), "r"(a[3]), "r"(b0), "r"(b1));
}
// fp16x4 (uint2) -> 4 floats
__device__ __forceinline__ void h4tof(uint2 u, float& a, float& b, float& c, float& d) {
    float2 f01 = __half22float2(*(__half2*)&u.x);
    float2 f23 = __half22float2(*(__half2*)&u.y);
    a = f01.x; b = f01.y; c = f23.x; d = f23.y;
}

// ---------------- dtype detection ----------------
__global__ void k_detect(const int* __restrict__ ei32) {
    int ornz = 0;
    #pragma unroll 8
    for (int j = 0; j < 256; j++) ornz |= ei32[2 * j + 1];
    g_is64 = (ornz == 0) ? 1 : 0;
}
__device__ __forceinline__ int edge_at(const int* ei32, int is64, long long idx) {
    return is64 ? ei32[2 * idx] : ei32[idx];
}

// ---------------- prolog ----------------
__global__ void k_deg_init() {
    int i = blockIdx.x * blockDim.x + threadIdx.x;
    if (i < NN) g_ideg[i] = 0;
    if (i < CC) { g_sum[i] = 0.f; g_sq[i] = 0.f; }
}
__global__ void k_deg(const int* __restrict__ ei32) {
    int e = blockIdx.x * blockDim.x + threadIdx.x;
    if (e < NE) {
        int c = edge_at(ei32, g_is64, (long long)NE + e);
        if ((unsigned)c < NN) atomicAdd(&g_ideg[c], 1);
    }
}
__global__ void k_dinv() {
    int i = blockIdx.x * blockDim.x + threadIdx.x;
    if (i < NN) g_dinv[i] = rsqrtf((float)(g_ideg[i] + 1));
}
__global__ void k_scan() {
    __shared__ int sh[1024];
    const int tid = threadIdx.x;
    const int per = 49;
    const int base = tid * per;
    int s = 0;
    for (int j = 0; j < per; j++) { int idx = base + j; if (idx < NN) s += g_ideg[idx]; }
    sh[tid] = s;
    __syncthreads();
    for (int d = 1; d < 1024; d <<= 1) {
        int v = (tid >= d) ? sh[tid - d] : 0;
        __syncthreads();
        sh[tid] += v;
        __syncthreads();
    }
    int run = (tid > 0) ? sh[tid - 1] : 0;
    for (int j = 0; j < per; j++) {
        int idx = base + j;
        if (idx < NN) { g_colptr[idx] = run; g_cursor[idx] = run; run += g_ideg[idx]; }
    }
    if (tid == 1023) g_colptr[NN] = sh[1023];
}
__global__ void k_fill(const int* __restrict__ ei32) {
    int e = blockIdx.x * blockDim.x + threadIdx.x;
    if (e < NE) {
        int is64 = g_is64;
        int r = edge_at(ei32, is64, e);
        int c = edge_at(ei32, is64, (long long)NE + e);
        if ((unsigned)r < NN && (unsigned)c < NN) {
            int pos = atomicAdd(&g_cursor[c], 1);
            g_src[pos] = r;
            g_w[pos] = g_dinv[r] * g_dinv[c];
        }
    }
}
// transpose + bf16 hi/lo split of all layer weights: Wt[l][n][k] = W[l][k][n]
__global__ void k_wprep(const float* __restrict__ W) {
    int idx = blockIdx.x * blockDim.x + threadIdx.x;
    if (idx < NL * CC * CC) {
        int l = idx / (CC * CC);
        int rem = idx - l * CC * CC;
        int n = rem / CC;
        int k = rem - n * CC;
        float v = W[(size_t)(l * CC + k) * CC + n];
        __nv_bfloat16 hi = __float2bfloat16_rn(v);
        float lo = v - __bfloat162float(hi);
        g_wt_hi[idx] = hi;
        g_wt_lo[idx] = __float2bfloat16_rn(lo);
    }
}

// ---------------- GEMM: H = X @ W via mma.sync bf16 hi/lo split ----------------
// Round-15 winner structure; epilogue now emits fp16 messages (half store traffic).
__global__ void __launch_bounds__(128, 4) k_gemm(const float* __restrict__ Xext,
                                                 int layer, int fused)
{
    __shared__ __align__(16) uint32_t s_hi[64 * SW];    // 17408 B
    __shared__ __align__(16) uint32_t s_lo[64 * SW];    // 17408 B
    __shared__ __align__(16) uint32_t s_whi[16 * SW];   // 4352 B (W chunk hi)
    __shared__ __align__(16) uint32_t s_wlo[16 * SW];   // 4352 B (W chunk lo)
    __shared__ float s_scale[CC], s_shift[CC];

    const int tid = threadIdx.x;
    const int row0 = blockIdx.x * 64;

    if (fused && tid < CC) { s_scale[tid] = g_scale[tid]; s_shift[tid] = g_shift[tid]; }
    __syncthreads();

    {   // convert X tile -> hi/lo bf16 into padded SMEM (zero-pad tail rows)
        const float4* src = fused ? ((const float4*)g_agg + (size_t)row0 * 32)
                                  : ((const float4*)(Xext + (size_t)row0 * CC));
        int rows = NN - row0; if (rows > 64) rows = 64;
        int n4 = rows * 32;
        #pragma unroll
        for (int i = 0; i < 16; i++) {
            int idx = tid + 128 * i;               // float4 index: row=idx>>5, c4=idx&31
            float4 v = make_float4(0.f, 0.f, 0.f, 0.f);
            if (idx < n4) v = src[idx];
            if (fused) {
                int ch = idx & 31;
                float4 sc = ((const float4*)s_scale)[ch];
                float4 sh = ((const float4*)s_shift)[ch];
                v.x = fmaxf(fmaf(v.x, sc.x, sh.x), 0.f);
                v.y = fmaxf(fmaf(v.y, sc.y, sh.y), 0.f);
                v.z = fmaxf(fmaf(v.z, sc.z, sh.z), 0.f);
                v.w = fmaxf(fmaf(v.w, sc.w, sh.w), 0.f);
            }
            int row = idx >> 5, c4 = idx & 31;
            int w0 = row * SW + c4 * 2;
            __nv_bfloat162 h0 = __floats2bfloat162_rn(v.x, v.y);
            __nv_bfloat162 h1 = __floats2bfloat162_rn(v.z, v.w);
            s_hi[w0 + 0] = *(uint32_t*)&h0;
            s_hi[w0 + 1] = *(uint32_t*)&h1;
            float rx = v.x - __low2float(h0),  ry = v.y - __high2float(h0);
            float rz = v.z - __low2float(h1),  rw = v.w - __high2float(h1);
            s_lo[w0 + 0] = bf2pack(rx, ry);
            s_lo[w0 + 1] = bf2pack(rz, rw);
        }
    }
    __syncthreads();

    const int wid = tid >> 5;
    const int lane = tid & 31;
    const int g = lane >> 2;        // 0..7
    const int tg = lane & 3;        // 0..3
    const int mrow = wid * 16;

    // hoist all A fragments (8 k-steps) into registers
    uint32_t ahi[8][4], alo[8][4];
    {
        const int ro = (mrow + g) * SW;
        const int r8 = (mrow + g + 8) * SW;
        #pragma unroll
        for (int ks = 0; ks < 8; ks++) {
            int kp = ks * 8 + tg;
            ahi[ks][0] = s_hi[ro + kp];     ahi[ks][1] = s_hi[r8 + kp];
            ahi[ks][2] = s_hi[ro + kp + 4]; ahi[ks][3] = s_hi[r8 + kp + 4];
            alo[ks][0] = s_lo[ro + kp];     alo[ks][1] = s_lo[r8 + kp];
            alo[ks][2] = s_lo[ro + kp + 4]; alo[ks][3] = s_lo[r8 + kp + 4];
        }
    }

    const uint4* whi = (const uint4*)(g_wt_hi + (size_t)layer * CC * CC);
    const uint4* wlo = (const uint4*)(g_wt_lo + (size_t)layer * CC * CC);
    const int r1 = row0 + mrow + g;
    const int r2 = r1 + 8;

    for (int c = 0; c < 8; c++) {          // 8 chunks of 16 output columns
        __syncthreads();
        {   // stage W chunk rows [16c, 16c+16) into padded SMEM
            int nl = tid >> 3;             // 0..15
            int seg = tid & 7;             // 0..7  (8 words = 2 uint4 per thread)
            int gsrc = (16 * c + nl) * 16 + seg * 2;   // uint4 index
            uint4 a = __ldg(&whi[gsrc]);
            uint4 b = __ldg(&whi[gsrc + 1]);
            uint4 e = __ldg(&wlo[gsrc]);
            uint4 f = __ldg(&wlo[gsrc + 1]);
            int dst = nl * SW + seg * 8;
            *(uint4*)&s_whi[dst] = a;
            *(uint4*)&s_whi[dst + 4] = b;
            *(uint4*)&s_wlo[dst] = e;
            *(uint4*)&s_wlo[dst + 4] = f;
        }
        __syncthreads();

        float acc[2][4];
        acc[0][0] = acc[0][1] = acc[0][2] = acc[0][3] = 0.f;
        acc[1][0] = acc[1][1] = acc[1][2] = acc[1][3] = 0.f;

        #pragma unroll
        for (int ks = 0; ks < 8; ks++) {
            int kp = ks * 8 + tg;
            #pragma unroll
            for (int ntl = 0; ntl < 2; ntl++) {
                int nloc = ntl * 8 + g;
                uint32_t bh0 = s_whi[nloc * SW + kp];
                uint32_t bh1 = s_whi[nloc * SW + kp + 4];
                uint32_t bl0 = s_wlo[nloc * SW + kp];
                uint32_t bl1 = s_wlo[nloc * SW + kp + 4];
                mma16816(acc[ntl], ahi[ks], bh0, bh1);
                mma16816(acc[ntl], ahi[ks], bl0, bl1);
                mma16816(acc[ntl], alo[ks], bh0, bh1);
            }
        }

        // per-chunk epilogue -> fp16 messages
        #pragma unroll
        for (int ntl = 0; ntl < 2; ntl++) {
            int col = c * 16 + ntl * 8 + tg * 2;
            if (r1 < NN) {
                __half2 h = __floats2half2_rn(acc[ntl][0], acc[ntl][1]);
                *(__half2*)&g_h[(size_t)r1 * CC + col] = h;
            }
            if (r2 < NN) {
                __half2 h = __floats2half2_rn(acc[ntl][2], acc[ntl][3]);
                *(__half2*)&g_h[(size_t)r2 * CC + col] = h;
            }
        }
    }
}

// ---------------- aggregation + fused BN stats (fp16 gather, fp32 accumulate) ----------------
__global__ void __launch_bounds__(256) k_aggregate()
{
    __shared__ float ssum[CC], ssq[CC];
    const int tid = threadIdx.x;
    if (tid < CC) { ssum[tid] = 0.f; ssq[tid] = 0.f; }
    __syncthreads();

    const int gw = (blockIdx.x * 256 + tid) >> 5;
    const int lane = tid & 31;
    const int nw = (gridDim.x * 256) >> 5;

    float s0 = 0, s1 = 0, s2 = 0, s3 = 0;
    float q0 = 0, q1 = 0, q2 = 0, q3 = 0;

    for (int i = gw; i < NN; i += nw) {
        float di = __ldg(&g_dinv[i]);
        float s2i = di * di;
        uint2 uv = __ldg((const uint2*)(g_h + (size_t)i * CC) + lane);
        float vx, vy, vz, vw; h4tof(uv, vx, vy, vz, vw);
        float4 acc = make_float4(vx * s2i, vy * s2i, vz * s2i, vw * s2i);

        int e0 = __ldg(&g_colptr[i]);
        int e1 = __ldg(&g_colptr[i + 1]);

        int e = e0;
        for (; e + 3 < e1; e += 4) {
            int   sA = __ldg(&g_src[e]);
            int   sB = __ldg(&g_src[e + 1]);
            int   sC = __ldg(&g_src[e + 2]);
            int   sD = __ldg(&g_src[e + 3]);
            float wA = __ldg(&g_w[e]);
            float wB = __ldg(&g_w[e + 1]);
            float wC = __ldg(&g_w[e + 2]);
            float wD = __ldg(&g_w[e + 3]);
            uint2 uA = __ldg((const uint2*)(g_h + (size_t)sA * CC) + lane);
            uint2 uB = __ldg((const uint2*)(g_h + (size_t)sB * CC) + lane);
            uint2 uC = __ldg((const uint2*)(g_h + (size_t)sC * CC) + lane);
            uint2 uD = __ldg((const uint2*)(g_h + (size_t)sD * CC) + lane);
            float ax, ay, az, aw; h4tof(uA, ax, ay, az, aw);
            float bx, by, bz, bw; h4tof(uB, bx, by, bz, bw);
            float cx, cy, cz, cw; h4tof(uC, cx, cy, cz, cw);
            float dx, dy, dz, dw; h4tof(uD, dx, dy, dz, dw);
            acc.x = fmaf(ax, wA, acc.x); acc.y = fmaf(ay, wA, acc.y);
            acc.z = fmaf(az, wA, acc.z); acc.w = fmaf(aw, wA, acc.w);
            acc.x = fmaf(bx, wB, acc.x); acc.y = fmaf(by, wB, acc.y);
            acc.z = fmaf(bz, wB, acc.z); acc.w = fmaf(bw, wB, acc.w);
            acc.x = fmaf(cx, wC, acc.x); acc.y = fmaf(cy, wC, acc.y);
            acc.z = fmaf(cz, wC, acc.z); acc.w = fmaf(cw, wC, acc.w);
            acc.x = fmaf(dx, wD, acc.x); acc.y = fmaf(dy, wD, acc.y);
            acc.z = fmaf(dz, wD, acc.z); acc.w = fmaf(dw, wD, acc.w);
        }
        for (; e < e1; e++) {
            int   s = __ldg(&g_src[e]);
            float wgt = __ldg(&g_w[e]);
            uint2 u = __ldg((const uint2*)(g_h + (size_t)s * CC) + lane);
            float ux, uy, uz, uw; h4tof(u, ux, uy, uz, uw);
            acc.x = fmaf(ux, wgt, acc.x); acc.y = fmaf(uy, wgt, acc.y);
            acc.z = fmaf(uz, wgt, acc.z); acc.w = fmaf(uw, wgt, acc.w);
        }

        *((float4*)(g_agg + (size_t)i * CC) + lane) = acc;

        s0 += acc.x; s1 += acc.y; s2 += acc.z; s3 += acc.w;
        q0 += acc.x * acc.x; q1 += acc.y * acc.y;
        q2 += acc.z * acc.z; q3 += acc.w * acc.w;
    }

    int ch = lane * 4;
    atomicAdd(&ssum[ch + 0], s0); atomicAdd(&ssum[ch + 1], s1);
    atomicAdd(&ssum[ch + 2], s2); atomicAdd(&ssum[ch + 3], s3);
    atomicAdd(&ssq[ch + 0], q0);  atomicAdd(&ssq[ch + 1], q1);
    atomicAdd(&ssq[ch + 2], q2);  atomicAdd(&ssq[ch + 3], q3);
    __syncthreads();
    if (tid < CC) {
        atomicAdd(&g_sum[tid], ssum[tid]);
        atomicAdd(&g_sq[tid], ssq[tid]);
    }
}

// ---------------- finalize BN params ----------------
__global__ void k_finalize(const float* __restrict__ gamma, const float* __restrict__ beta)
{
    int c = threadIdx.x;
    float mu = g_sum[c] * (1.0f / NN);
    float var = g_sq[c] * (1.0f / NN) - mu * mu;
    float rstd = rsqrtf(var + BN_EPS);
    float sc = rstd * gamma[c];
    g_scale[c] = sc;
    g_shift[c] = beta[c] - mu * sc;
    g_sum[c] = 0.f; g_sq[c] = 0.f;
}

// ---------------- final normalize + relu -> out ----------------
__global__ void __launch_bounds__(256) k_norm_relu(float* __restrict__ OUT)
{
    __shared__ float4 ssc[32], ssh[32];
    const int tid = threadIdx.x;
    if (tid < 32) {
        ssc[tid] = ((const float4*)g_scale)[tid];
        ssh[tid] = ((const float4*)g_shift)[tid];
    }
    __syncthreads();
    const int stride = gridDim.x * 256;
    const float4* A = (const float4*)g_agg;
    float4* O = (float4*)OUT;
    for (int f = blockIdx.x * 256 + tid; f < NC4; f += stride) {
        int ch = f & 31;
        float4 v = A[f];
        float4 sc = ssc[ch];
        float4 sh = ssh[ch];
        float4 o;
        o.x = fmaxf(fmaf(v.x, sc.x, sh.x), 0.f);
        o.y = fmaxf(fmaf(v.y, sc.y, sh.y), 0.f);
        o.z = fmaxf(fmaf(v.z, sc.z, sh.z), 0.f);
        o.w = fmaxf(fmaf(v.w, sc.w, sh.w), 0.f);
        O[f] = o;
    }
}

// ---------------- launch ----------------
extern "C" void kernel_launch(void* const* d_in, const int* in_sizes, int n_in,
                              void* d_out, int out_size)
{
    const float* x     = (const float*)d_in[0];
    const int*   ei32  = (const int*)d_in[1];
    const float* W     = (const float*)d_in[2];
    const float* gamma = (const float*)d_in[4];
    const float* beta  = (const float*)d_in[5];
    float*       out   = (float*)d_out;

    k_detect<<<1, 1>>>(ei32);
    k_deg_init<<<(NN + 255) / 256, 256>>>();
    k_deg<<<(NE + 255) / 256, 256>>>(ei32);
    k_dinv<<<(NN + 255) / 256, 256>>>();
    k_scan<<<1, 1024>>>();
    k_fill<<<(NE + 255) / 256, 256>>>(ei32);
    k_wprep<<<(NL * CC * CC + 255) / 256, 256>>>(W);

    const int GEMM_BLOCKS = (NN + 63) / 64;   // 782
    const int AGG_BLOCKS  = 1184;
    const int EW_BLOCKS   = 1184;

    for (int l = 0; l < NL; l++) {
        k_gemm<<<GEMM_BLOCKS, 128>>>(x, l, (l != 0));
        k_aggregate<<<AGG_BLOCKS, 256>>>();
        k_finalize<<<1, CC>>>(gamma + l * CC, beta + l * CC);
    }
    k_norm_relu<<<EW_BLOCKS, 256>>>(out);
    (void)in_sizes; (void)n_in; (void)out_size;
}

// round 17
// speedup vs baseline: 1.6669x; 1.0443x over previous
#include <cuda_runtime.h>
#include <cuda_bf16.h>
#include <cuda_fp16.h>
#include <cstdint>

#define NN 50000
#define NE 800000
#define CC 128
#define NL 4
#define BN_EPS 1e-5f
#define NC4 (NN * (CC / 4))
#define SW 68   // padded row stride in 32-bit words: bank = (4*row + kp) % 32 -> conflict-free

// ---------------- scratch (static device globals; no allocation) ----------------
__device__ int   g_is64;
__device__ __align__(16) int   g_ideg[NN];
__device__ __align__(16) float g_dinv[NN];
__device__ __align__(16) int   g_colptr[NN + 1];
__device__ __align__(16) int   g_cursor[NN];
__device__ __align__(16) int2  g_srcw[NE];       // packed {src, w-bits} per edge
__device__ __align__(16) __half g_h[NN * CC];    // messages in fp16
__device__ __align__(16) float g_agg[NN * CC];
__device__ __align__(16) float g_sum[CC];
__device__ __align__(16) float g_sq[CC];
__device__ __align__(16) float g_scale[CC];
__device__ __align__(16) float g_shift[CC];
// W transposed + bf16 hi/lo split: Wt[l][n][k] (n = out channel, k contiguous)
__device__ __align__(16) __nv_bfloat16 g_wt_hi[NL * CC * CC];
__device__ __align__(16) __nv_bfloat16 g_wt_lo[NL * CC * CC];

// ---------------- helpers ----------------
__device__ __forceinline__ uint32_t bf2pack(float a, float b) {
    __nv_bfloat162 t = __floats2bfloat162_rn(a, b);
    return *(uint32_t*)&t;
}
// mma.sync m16n8k16 row.col bf16 -> fp32 accumulate (baseline PTX, sm_80+)
__device__ __forceinline__ void mma16816(float* d, const uint32_t* a, uint32_t b0, uint32_t b1) {
    asm volatile(
        "mma.sync.aligned.m16n8k16.row.col.f32.bf16.bf16.f32 "
        "{%0,%1,%2,%3}, {%4,%5,%6,%7}, {%8,%9}, {%0,%1,%2,%3};"
        : "+f"(d[0]), "+f"(d[1]), "+f"(d[2]), "+f"(d[3])
        : "r"(a[0]), "r"(a[1]), "r"(a[2]), "r"(a[3]), "r"(b0), "r"(b1));
}
// fp16x4 (uint2) -> 4 floats
__device__ __forceinline__ void h4tof(uint2 u, float& a, float& b, float& c, float& d) {
    float2 f01 = __half22float2(*(__half2*)&u.x);
    float2 f23 = __half22float2(*(__half2*)&u.y);
    a = f01.x; b = f01.y; c = f23.x; d = f23.y;
}
__device__ __forceinline__ int edge_at(const int* ei32, int is64, long long idx) {
    return is64 ? ei32[2 * idx] : ei32[idx];
}

// ---------------- prolog ----------------
// init scratch + PARALLEL dtype detection (block 0: 256-thread OR-reduce over the
// high words of the first 256 entries; int64 storage -> all zero).
__global__ void k_init(const int* __restrict__ ei32) {
    int i = blockIdx.x * blockDim.x + threadIdx.x;
    if (i < NN) g_ideg[i] = 0;
    if (i < CC) { g_sum[i] = 0.f; g_sq[i] = 0.f; }
    if (blockIdx.x == 0) {
        int v = ei32[2 * threadIdx.x + 1];
        int any = __syncthreads_or(v != 0);
        if (threadIdx.x == 0) g_is64 = any ? 0 : 1;
    }
}
__global__ void k_deg(const int* __restrict__ ei32) {
    int e = blockIdx.x * blockDim.x + threadIdx.x;
    if (e < NE) {
        int c = edge_at(ei32, g_is64, (long long)NE + e);
        if ((unsigned)c < NN) atomicAdd(&g_ideg[c], 1);
    }
}
__global__ void k_dinv() {
    int i = blockIdx.x * blockDim.x + threadIdx.x;
    if (i < NN) g_dinv[i] = rsqrtf((float)(g_ideg[i] + 1));
}
__global__ void k_scan() {
    __shared__ int sh[1024];
    const int tid = threadIdx.x;
    const int per = 49;
    const int base = tid * per;
    int s = 0;
    for (int j = 0; j < per; j++) { int idx = base + j; if (idx < NN) s += g_ideg[idx]; }
    sh[tid] = s;
    __syncthreads();
    for (int d = 1; d < 1024; d <<= 1) {
        int v = (tid >= d) ? sh[tid - d] : 0;
        __syncthreads();
        sh[tid] += v;
        __syncthreads();
    }
    int run = (tid > 0) ? sh[tid - 1] : 0;
    for (int j = 0; j < per; j++) {
        int idx = base + j;
        if (idx < NN) { g_colptr[idx] = run; g_cursor[idx] = run; run += g_ideg[idx]; }
    }
    if (tid == 1023) g_colptr[NN] = sh[1023];
}
__global__ void k_fill(const int* __restrict__ ei32) {
    int e = blockIdx.x * blockDim.x + threadIdx.x;
    if (e < NE) {
        int is64 = g_is64;
        int r = edge_at(ei32, is64, e);
        int c = edge_at(ei32, is64, (long long)NE + e);
        if ((unsigned)r < NN && (unsigned)c < NN) {
            int pos = atomicAdd(&g_cursor[c], 1);
            float w = g_dinv[r] * g_dinv[c];
            g_srcw[pos] = make_int2(r, __float_as_int(w));
        }
    }
}
// transpose + bf16 hi/lo split of all layer weights: Wt[l][n][k] = W[l][k][n]
__global__ void k_wprep(const float* __restrict__ W) {
    int idx = blockIdx.x * blockDim.x + threadIdx.x;
    if (idx < NL * CC * CC) {
        int l = idx / (CC * CC);
        int rem = idx - l * CC * CC;
        int n = rem / CC;
        int k = rem - n * CC;
        float v = W[(size_t)(l * CC + k) * CC + n];
        __nv_bfloat16 hi = __float2bfloat16_rn(v);
        float lo = v - __bfloat162float(hi);
        g_wt_hi[idx] = hi;
        g_wt_lo[idx] = __float2bfloat16_rn(lo);
    }
}

// ---------------- GEMM: H = X @ W via mma.sync bf16 hi/lo split ----------------
__global__ void __launch_bounds__(128, 4) k_gemm(const float* __restrict__ Xext,
                                                 int layer, int fused)
{
    __shared__ __align__(16) uint32_t s_hi[64 * SW];    // 17408 B
    __shared__ __align__(16) uint32_t s_lo[64 * SW];    // 17408 B
    __shared__ __align__(16) uint32_t s_whi[16 * SW];   // 4352 B (W chunk hi)
    __shared__ __align__(16) uint32_t s_wlo[16 * SW];   // 4352 B (W chunk lo)
    __shared__ float s_scale[CC], s_shift[CC];

    const int tid = threadIdx.x;
    const int row0 = blockIdx.x * 64;

    if (fused && tid < CC) { s_scale[tid] = g_scale[tid]; s_shift[tid] = g_shift[tid]; }
    __syncthreads();

    {   // convert X tile -> hi/lo bf16 into padded SMEM (zero-pad tail rows)
        const float4* src = fused ? ((const float4*)g_agg + (size_t)row0 * 32)
                                  : ((const float4*)(Xext + (size_t)row0 * CC));
        int rows = NN - row0; if (rows > 64) rows = 64;
        int n4 = rows * 32;
        #pragma unroll
        for (int i = 0; i < 16; i++) {
            int idx = tid + 128 * i;
            float4 v = make_float4(0.f, 0.f, 0.f, 0.f);
            if (idx < n4) v = src[idx];
            if (fused) {
                int ch = idx & 31;
                float4 sc = ((const float4*)s_scale)[ch];
                float4 sh = ((const float4*)s_shift)[ch];
                v.x = fmaxf(fmaf(v.x, sc.x, sh.x), 0.f);
                v.y = fmaxf(fmaf(v.y, sc.y, sh.y), 0.f);
                v.z = fmaxf(fmaf(v.z, sc.z, sh.z), 0.f);
                v.w = fmaxf(fmaf(v.w, sc.w, sh.w), 0.f);
            }
            int row = idx >> 5, c4 = idx & 31;
            int w0 = row * SW + c4 * 2;
            __nv_bfloat162 h0 = __floats2bfloat162_rn(v.x, v.y);
            __nv_bfloat162 h1 = __floats2bfloat162_rn(v.z, v.w);
            s_hi[w0 + 0] = *(uint32_t*)&h0;
            s_hi[w0 + 1] = *(uint32_t*)&h1;
            float rx = v.x - __low2float(h0),  ry = v.y - __high2float(h0);
            float rz = v.z - __low2float(h1),  rw = v.w - __high2float(h1);
            s_lo[w0 + 0] = bf2pack(rx, ry);
            s_lo[w0 + 1] = bf2pack(rz, rw);
        }
    }
    __syncthreads();

    const int wid = tid >> 5;
    const int lane = tid & 31;
    const int g = lane >> 2;
    const int tg = lane & 3;
    const int mrow = wid * 16;

    uint32_t ahi[8][4], alo[8][4];
    {
        const int ro = (mrow + g) * SW;
        const int r8 = (mrow + g + 8) * SW;
        #pragma unroll
        for (int ks = 0; ks < 8; ks++) {
            int kp = ks * 8 + tg;
            ahi[ks][0] = s_hi[ro + kp];     ahi[ks][1] = s_hi[r8 + kp];
            ahi[ks][2] = s_hi[ro + kp + 4]; ahi[ks][3] = s_hi[r8 + kp + 4];
            alo[ks][0] = s_lo[ro + kp];     alo[ks][1] = s_lo[r8 + kp];
            alo[ks][2] = s_lo[ro + kp + 4]; alo[ks][3] = s_lo[r8 + kp + 4];
        }
    }

    const uint4* whi = (const uint4*)(g_wt_hi + (size_t)layer * CC * CC);
    const uint4* wlo = (const uint4*)(g_wt_lo + (size_t)layer * CC * CC);
    const int r1 = row0 + mrow + g;
    const int r2 = r1 + 8;

    for (int c = 0; c < 8; c++) {
        __syncthreads();
        {   // stage W chunk rows [16c, 16c+16)
            int nl = tid >> 3;
            int seg = tid & 7;
            int gsrc = (16 * c + nl) * 16 + seg * 2;
            uint4 a = __ldg(&whi[gsrc]);
            uint4 b = __ldg(&whi[gsrc + 1]);
            uint4 e = __ldg(&wlo[gsrc]);
            uint4 f = __ldg(&wlo[gsrc + 1]);
            int dst = nl * SW + seg * 8;
            *(uint4*)&s_whi[dst] = a;
            *(uint4*)&s_whi[dst + 4] = b;
            *(uint4*)&s_wlo[dst] = e;
            *(uint4*)&s_wlo[dst + 4] = f;
        }
        __syncthreads();

        float acc[2][4];
        acc[0][0] = acc[0][1] = acc[0][2] = acc[0][3] = 0.f;
        acc[1][0] = acc[1][1] = acc[1][2] = acc[1][3] = 0.f;

        #pragma unroll
        for (int ks = 0; ks < 8; ks++) {
            int kp = ks * 8 + tg;
            #pragma unroll
            for (int ntl = 0; ntl < 2; ntl++) {
                int nloc = ntl * 8 + g;
                uint32_t bh0 = s_whi[nloc * SW + kp];
                uint32_t bh1 = s_whi[nloc * SW + kp + 4];
                uint32_t bl0 = s_wlo[nloc * SW + kp];
                uint32_t bl1 = s_wlo[nloc * SW + kp + 4];
                mma16816(acc[ntl], ahi[ks], bh0, bh1);
                mma16816(acc[ntl], ahi[ks], bl0, bl1);
                mma16816(acc[ntl], alo[ks], bh0, bh1);
            }
        }

        #pragma unroll
        for (int ntl = 0; ntl < 2; ntl++) {
            int col = c * 16 + ntl * 8 + tg * 2;
            if (r1 < NN) {
                __half2 h = __floats2half2_rn(acc[ntl][0], acc[ntl][1]);
                *(__half2*)&g_h[(size_t)r1 * CC + col] = h;
            }
            if (r2 < NN) {
                __half2 h = __floats2half2_rn(acc[ntl][2], acc[ntl][3]);
                *(__half2*)&g_h[(size_t)r2 * CC + col] = h;
            }
        }
    }
}

// ---------------- aggregation + fused BN stats (fp16 gather, packed metadata) ----------------
__global__ void __launch_bounds__(256) k_aggregate()
{
    __shared__ float ssum[CC], ssq[CC];
    const int tid = threadIdx.x;
    if (tid < CC) { ssum[tid] = 0.f; ssq[tid] = 0.f; }
    __syncthreads();

    const int gw = (blockIdx.x * 256 + tid) >> 5;
    const int lane = tid & 31;
    const int nw = (gridDim.x * 256) >> 5;

    float s0 = 0, s1 = 0, s2 = 0, s3 = 0;
    float q0 = 0, q1 = 0, q2 = 0, q3 = 0;

    for (int i = gw; i < NN; i += nw) {
        float di = __ldg(&g_dinv[i]);
        float s2i = di * di;
        uint2 uv = __ldg((const uint2*)(g_h + (size_t)i * CC) + lane);
        float vx, vy, vz, vw; h4tof(uv, vx, vy, vz, vw);
        float4 acc = make_float4(vx * s2i, vy * s2i, vz * s2i, vw * s2i);

        int e0 = __ldg(&g_colptr[i]);
        int e1 = __ldg(&g_colptr[i + 1]);

        int e = e0;
        for (; e + 3 < e1; e += 4) {
            int2 mA = __ldg(&g_srcw[e]);
            int2 mB = __ldg(&g_srcw[e + 1]);
            int2 mC = __ldg(&g_srcw[e + 2]);
            int2 mD = __ldg(&g_srcw[e + 3]);
            uint2 uA = __ldg((const uint2*)(g_h + (size_t)mA.x * CC) + lane);
            uint2 uB = __ldg((const uint2*)(g_h + (size_t)mB.x * CC) + lane);
            uint2 uC = __ldg((const uint2*)(g_h + (size_t)mC.x * CC) + lane);
            uint2 uD = __ldg((const uint2*)(g_h + (size_t)mD.x * CC) + lane);
            float wA = __int_as_float(mA.y), wB = __int_as_float(mB.y);
            float wC = __int_as_float(mC.y), wD = __int_as_float(mD.y);
            float ax, ay, az, aw; h4tof(uA, ax, ay, az, aw);
            float bx, by, bz, bw; h4tof(uB, bx, by, bz, bw);
            float cx, cy, cz, cw; h4tof(uC, cx, cy, cz, cw);
            float dx, dy, dz, dw; h4tof(uD, dx, dy, dz, dw);
            acc.x = fmaf(ax, wA, acc.x); acc.y = fmaf(ay, wA, acc.y);
            acc.z = fmaf(az, wA, acc.z); acc.w = fmaf(aw, wA, acc.w);
            acc.x = fmaf(bx, wB, acc.x); acc.y = fmaf(by, wB, acc.y);
            acc.z = fmaf(bz, wB, acc.z); acc.w = fmaf(bw, wB, acc.w);
            acc.x = fmaf(cx, wC, acc.x); acc.y = fmaf(cy, wC, acc.y);
            acc.z = fmaf(cz, wC, acc.z); acc.w = fmaf(cw, wC, acc.w);
            acc.x = fmaf(dx, wD, acc.x); acc.y = fmaf(dy, wD, acc.y);
            acc.z = fmaf(dz, wD, acc.z); acc.w = fmaf(dw, wD, acc.w);
        }
        for (; e < e1; e++) {
            int2 m = __ldg(&g_srcw[e]);
            uint2 u = __ldg((const uint2*)(g_h + (size_t)m.x * CC) + lane);
            float wgt = __int_as_float(m.y);
            float ux, uy, uz, uw; h4tof(u, ux, uy, uz, uw);
            acc.x = fmaf(ux, wgt, acc.x); acc.y = fmaf(uy, wgt, acc.y);
            acc.z = fmaf(uz, wgt, acc.z); acc.w = fmaf(uw, wgt, acc.w);
        }

        *((float4*)(g_agg + (size_t)i * CC) + lane) = acc;

        s0 += acc.x; s1 += acc.y; s2 += acc.z; s3 += acc.w;
        q0 += acc.x * acc.x; q1 += acc.y * acc.y;
        q2 += acc.z * acc.z; q3 += acc.w * acc.w;
    }

    int ch = lane * 4;
    atomicAdd(&ssum[ch + 0], s0); atomicAdd(&ssum[ch + 1], s1);
    atomicAdd(&ssum[ch + 2], s2); atomicAdd(&ssum[ch + 3], s3);
    atomicAdd(&ssq[ch + 0], q0);  atomicAdd(&ssq[ch + 1], q1);
    atomicAdd(&ssq[ch + 2], q2);  atomicAdd(&ssq[ch + 3], q3);
    __syncthreads();
    if (tid < CC) {
        atomicAdd(&g_sum[tid], ssum[tid]);
        atomicAdd(&g_sq[tid], ssq[tid]);
    }
}

// ---------------- finalize BN params ----------------
__global__ void k_finalize(const float* __restrict__ gamma, const float* __restrict__ beta)
{
    int c = threadIdx.x;
    float mu = g_sum[c] * (1.0f / NN);
    float var = g_sq[c] * (1.0f / NN) - mu * mu;
    float rstd = rsqrtf(var + BN_EPS);
    float sc = rstd * gamma[c];
    g_scale[c] = sc;
    g_shift[c] = beta[c] - mu * sc;
    g_sum[c] = 0.f; g_sq[c] = 0.f;
}

// ---------------- final normalize + relu -> out ----------------
__global__ void __launch_bounds__(256) k_norm_relu(float* __restrict__ OUT)
{
    __shared__ float4 ssc[32], ssh[32];
    const int tid = threadIdx.x;
    if (tid < 32) {
        ssc[tid] = ((const float4*)g_scale)[tid];
        ssh[tid] = ((const float4*)g_shift)[tid];
    }
    __syncthreads();
    const int stride = gridDim.x * 256;
    const float4* A = (const float4*)g_agg;
    float4* O = (float4*)OUT;
    for (int f = blockIdx.x * 256 + tid; f < NC4; f += stride) {
        int ch = f & 31;
        float4 v = A[f];
        float4 sc = ssc[ch];
        float4 sh = ssh[ch];
        float4 o;
        o.x = fmaxf(fmaf(v.x, sc.x, sh.x), 0.f);
        o.y = fmaxf(fmaf(v.y, sc.y, sh.y), 0.f);
        o.z = fmaxf(fmaf(v.z, sc.z, sh.z), 0.f);
        o.w = fmaxf(fmaf(v.w, sc.w, sh.w), 0.f);
        O[f] = o;
    }
}

// ---------------- launch ----------------
extern "C" void kernel_launch(void* const* d_in, const int* in_sizes, int n_in,
                              void* d_out, int out_size)
{
    const float* x     = (const float*)d_in[0];
    const int*   ei32  = (const int*)d_in[1];
    const float* W     = (const float*)d_in[2];
    const float* gamma = (const float*)d_in[4];
    const float* beta  = (const float*)d_in[5];
    float*       out   = (float*)d_out;

    k_init<<<(NN + 255) / 256, 256>>>(ei32);
    k_deg<<<(NE + 255) / 256, 256>>>(ei32);
    k_dinv<<<(NN + 255) / 256, 256>>>();
    k_scan<<<1, 1024>>>();
    k_fill<<<(NE + 255) / 256, 256>>>(ei32);
    k_wprep<<<(NL * CC * CC + 255) / 256, 256>>>(W);

    const int GEMM_BLOCKS = (NN + 63) / 64;   // 782
    const int AGG_BLOCKS  = 1184;
    const int EW_BLOCKS   = 1184;

    for (int l = 0; l < NL; l++) {
        k_gemm<<<GEMM_BLOCKS, 128>>>(x, l, (l != 0));
        k_aggregate<<<AGG_BLOCKS, 256>>>();
        k_finalize<<<1, CC>>>(gamma + l * CC, beta + l * CC);
    }
    k_norm_relu<<<EW_BLOCKS, 256>>>(out);
    (void)in_sizes; (void)n_in; (void)out_size;
}